// round 7
// baseline (speedup 1.0000x reference)
#include <cuda_runtime.h>
#include <cstdint>
#include <cstddef>
#include <math.h>

// Problem constants (fixed by the reference: B=8, N=4096, NITER=4)
constexpr int B = 8;
constexpr int N = 4096;
constexpr int NITER = 4;
constexpr int BN = B * N;

constexpr int NCHUNK = 32;          // b-dimension split
constexpr int CB = N / NCHUNK;      // 128 P-rows per chunk
constexpr int TILE_A = 128;         // output columns per block
constexpr int NTILE = N / TILE_A;   // 32 a-tiles
constexpr int BLOCK_A = 128;        // 32 col-quads x 4 batch-pairs

// Static scratch (no allocations allowed)
__device__ float g_part[(size_t)NCHUNK * BN];   // 4 MB partial sums
__device__ float g_pred[BN];                    // current pred between iterations
__device__ unsigned int g_cnt[NTILE];           // arrival counters (zero-init; reset by last block)

using ull = unsigned long long;

__device__ __forceinline__ ull pk2(float x) {
    ull r; asm("mov.b64 %0, {%1, %1};" : "=l"(r) : "f"(x)); return r;
}
__device__ __forceinline__ ull fma2(ull a, ull b, ull c) {
    ull d; asm("fma.rn.f32x2 %0, %1, %2, %3;" : "=l"(d) : "l"(a), "l"(b), "l"(c)); return d;
}
__device__ __forceinline__ void upk2(ull v, float& lo, float& hi) {
    asm("mov.b64 {%0, %1}, %2;" : "=f"(lo), "=f"(hi) : "l"(v));
}

// Fused kernel, one launch per diffusion iteration.
// Grid (NTILE=32, NCHUNK=32) = 1024 blocks x 128 threads (~28 warps/SM).
//
// Phase 1 (all blocks): partial sums S_c[i,a] = sum_{b in chunk c} pred[i,b]*P[b,a]
//   Thread (q,p): column quad q (4 consecutive a), batch pair p. The 4 lanes of a
//   quad load the SAME P float4 -> warp-dedup; one 128B line per warp per row.
//
// Phase 2 (last-arriving block per a-tile): sum the 32 L2-hot planes for this
//   tile's 128 columns x 8 batches, v = 1-exp(-S), seed clamp, write pred/out.
__global__ void __launch_bounds__(BLOCK_A, 8) prop(
    const float* __restrict__ P, const float* __restrict__ pred0,
    const int2* __restrict__ seed, int nseeds,
    int use_ext, float* __restrict__ final_out)
{
    __shared__ ull s_p2[CB * 4];                  // pred chunk, batch-paired (4 KB)
    __shared__ int s_last;
    float* s_f = reinterpret_cast<float*>(s_p2);  // s_f[b*8 + i] = pred[i][b0+b]

    const int tid = threadIdx.x;
    const int c = blockIdx.y;
    const int b0 = c * CB;
    const float* __restrict__ pred = use_ext ? pred0 : g_pred;

#pragma unroll
    for (int j = 0; j < (CB * B) / BLOCK_A; j++) {   // 8 per thread
        int idx = j * BLOCK_A + tid;
        int i = idx >> 7;          // batch 0..7
        int b = idx & (CB - 1);    // local row 0..127
        s_f[b * 8 + i] = pred[i * N + b0 + b];
    }
    __syncthreads();

    const int q = tid >> 2;        // col quad 0..31
    const int p = tid & 3;         // batch pair 0..3
    const int a0 = blockIdx.x * TILE_A + q * 4;
    const float4* __restrict__ p4 =
        reinterpret_cast<const float4*>(P + (size_t)b0 * N) + (a0 >> 2);

    ull acc0 = 0, acc1 = 0, acc2 = 0, acc3 = 0;   // f32x2 per column

#pragma unroll 4
    for (int b = 0; b < CB; b++) {
        float4 pv = __ldg(&p4[(size_t)b * (N >> 2)]);
        ull np = s_p2[b * 4 + p];
        acc0 = fma2(pk2(pv.x), np, acc0);
        acc1 = fma2(pk2(pv.y), np, acc1);
        acc2 = fma2(pk2(pv.z), np, acc2);
        acc3 = fma2(pk2(pv.w), np, acc3);
    }

    // Store this chunk's partial plane: cols a0..a0+3, batches 2p (lo) / 2p+1 (hi).
    {
        float lo0, hi0, lo1, hi1, lo2, hi2, lo3, hi3;
        upk2(acc0, lo0, hi0); upk2(acc1, lo1, hi1);
        upk2(acc2, lo2, hi2); upk2(acc3, lo3, hi3);
        float* outc = g_part + (size_t)c * BN;
        *reinterpret_cast<float4*>(outc + (size_t)(2 * p) * N + a0) =
            make_float4(lo0, lo1, lo2, lo3);
        *reinterpret_cast<float4*>(outc + (size_t)(2 * p + 1) * N + a0) =
            make_float4(hi0, hi1, hi2, hi3);
    }

    // Last-block-arrival detection.
    __syncthreads();
    if (tid == 0) {
        __threadfence();
        unsigned int old = atomicAdd(&g_cnt[blockIdx.x], 1u);
        s_last = (old == NCHUNK - 1) ? 1 : 0;
        if (s_last) __threadfence();
    }
    __syncthreads();
    if (!s_last) return;

    // ---- Combine phase (one block per a-tile; planes are L2-hot) ----
    const int A0 = blockIdx.x * TILE_A;
    const float4* __restrict__ part4 = reinterpret_cast<const float4*>(g_part);
    float4* __restrict__ pred4 = reinterpret_cast<float4*>(g_pred);
    float4* __restrict__ out4 = reinterpret_cast<float4*>(final_out);

    // Tile outputs: 128 cols x 8 batches = 256 float4 quads; 2 per thread.
    // quad qA = tid (batches 0..3), quad qB = tid + 128 (batches 4..7).
    const int aq = tid & 31;
    const int addrA = ((tid >> 5) + 0) * (N >> 2) + (A0 >> 2) + aq;
    const int addrB = ((tid >> 5) + 4) * (N >> 2) + (A0 >> 2) + aq;

    float4 accA = make_float4(0.f, 0.f, 0.f, 0.f);
    float4 accB = make_float4(0.f, 0.f, 0.f, 0.f);
#pragma unroll 4
    for (int cc = 0; cc < NCHUNK; cc++) {
        float4 va = __ldg(&part4[(size_t)cc * (BN >> 2) + addrA]);
        float4 vb = __ldg(&part4[(size_t)cc * (BN >> 2) + addrB]);
        accA.x += va.x; accA.y += va.y; accA.z += va.z; accA.w += va.w;
        accB.x += vb.x; accB.y += vb.y; accB.z += vb.z; accB.w += vb.w;
    }

    float4 rA, rB;
    rA.x = 1.0f - __expf(-accA.x);
    rA.y = 1.0f - __expf(-accA.y);
    rA.z = 1.0f - __expf(-accA.z);
    rA.w = 1.0f - __expf(-accA.w);
    rB.x = 1.0f - __expf(-accB.x);
    rB.y = 1.0f - __expf(-accB.y);
    rB.z = 1.0f - __expf(-accB.z);
    rB.w = 1.0f - __expf(-accB.w);
    pred4[addrA] = rA;
    pred4[addrB] = rB;
    if (final_out) { out4[addrA] = rA; out4[addrB] = rB; }

    __syncthreads();   // quad stores before seed overwrites
    for (int s = tid; s < nseeds; s += BLOCK_A) {
        int2 sd = seed[s];
        int n = sd.y;
        if (n >= A0 && n < A0 + TILE_A) {
            g_pred[sd.x * N + n] = 1.0f;
            if (final_out) final_out[sd.x * N + n] = 1.0f;
        }
    }
    if (tid == 0) g_cnt[blockIdx.x] = 0;   // reset for next launch/replay
}

extern "C" void kernel_launch(void* const* d_in, const int* in_sizes, int n_in,
                              void* d_out, int out_size) {
    const float* preds = (const float*)d_in[0];      // [B, N] fp32
    const float* P = (const float*)d_in[1];          // [N, N] fp32, P[b*N + a]
    const int2* seed = (const int2*)d_in[2];         // [NSEEDS, 2] int32 (b, n)
    int nseeds = in_sizes[2] / 2;
    float* out = (float*)d_out;

    dim3 grid(NTILE, NCHUNK);   // (32, 32) = 1024 blocks

    for (int t = 0; t < NITER; t++) {
        prop<<<grid, BLOCK_A>>>(P, preds, seed, nseeds,
                                t == 0 ? 1 : 0,
                                (t == NITER - 1) ? out : nullptr);
    }
}

// round 10
// speedup vs baseline: 1.1590x; 1.1590x over previous
#include <cuda_runtime.h>
#include <cstdint>
#include <cstddef>
#include <math.h>

// Problem constants (fixed by the reference: B=8, N=4096, NITER=4)
constexpr int B = 8;
constexpr int N = 4096;
constexpr int NITER = 4;
constexpr int BN = B * N;

constexpr int NCHUNK = 32;          // b-dimension split
constexpr int CB = N / NCHUNK;      // 128 P-rows per chunk
constexpr int TILE_A = 128;         // output columns per block
constexpr int NTILE = N / TILE_A;   // 32 a-tiles
constexpr int BLOCK_A = 128;        // 32 col-quads x 4 batch-pairs

// Static scratch (no allocations allowed)
__device__ float g_part[(size_t)NCHUNK * BN];   // 4 MB partial sums
__device__ float g_pred[BN];                    // current pred between iterations

using ull = unsigned long long;

__device__ __forceinline__ ull pk2(float x) {
    ull r; asm("mov.b64 %0, {%1, %1};" : "=l"(r) : "f"(x)); return r;
}
__device__ __forceinline__ ull fma2(ull a, ull b, ull c) {
    ull d; asm("fma.rn.f32x2 %0, %1, %2, %3;" : "=l"(d) : "l"(a), "l"(b), "l"(c)); return d;
}
__device__ __forceinline__ void upk2(ull v, float& lo, float& hi) {
    asm("mov.b64 {%0, %1}, %2;" : "=f"(lo), "=f"(hi) : "l"(v));
}

// Kernel A: partial sums S_c[i,a] = sum_{b in chunk c} pred[i,b] * P[b,a].
// Grid (NTILE=32, NCHUNK=32) = 1024 blocks x 128 threads (~28 warps/SM).
// Thread (q, p): column quad q (4 consecutive a), batch pair p (batches 2p, 2p+1).
// The 4 lanes of a quad load the SAME P float4 -> warp dedup; 128B/warp/row.
__global__ void __launch_bounds__(BLOCK_A, 8) propA(
    const float* __restrict__ P, const float* __restrict__ pred0, int use_ext)
{
    __shared__ ull s_p2[CB * 4];                  // pred chunk, batch-paired (4 KB)
    float* s_f = reinterpret_cast<float*>(s_p2);  // s_f[b*8 + i] = pred[i][b0+b]

    const int tid = threadIdx.x;
    const int c = blockIdx.y;
    const int b0 = c * CB;
    const float* __restrict__ pred = use_ext ? pred0 : g_pred;

#pragma unroll
    for (int j = 0; j < (CB * B) / BLOCK_A; j++) {   // 8 per thread
        int idx = j * BLOCK_A + tid;
        int i = idx >> 7;          // batch 0..7
        int b = idx & (CB - 1);    // local row 0..127
        s_f[b * 8 + i] = pred[i * N + b0 + b];
    }
    __syncthreads();

    const int q = tid >> 2;        // col quad 0..31
    const int p = tid & 3;         // batch pair 0..3
    const int a0 = blockIdx.x * TILE_A + q * 4;
    const float4* __restrict__ p4 =
        reinterpret_cast<const float4*>(P + (size_t)b0 * N) + (a0 >> 2);

    ull acc0 = 0, acc1 = 0, acc2 = 0, acc3 = 0;   // f32x2 per column

#pragma unroll 8
    for (int b = 0; b < CB; b++) {
        float4 pv = __ldg(&p4[(size_t)b * (N >> 2)]);
        ull np = s_p2[b * 4 + p];
        acc0 = fma2(pk2(pv.x), np, acc0);
        acc1 = fma2(pk2(pv.y), np, acc1);
        acc2 = fma2(pk2(pv.z), np, acc2);
        acc3 = fma2(pk2(pv.w), np, acc3);
    }

    // Store: cols a0..a0+3 for batches 2p (lo) and 2p+1 (hi).
    float lo0, hi0, lo1, hi1, lo2, hi2, lo3, hi3;
    upk2(acc0, lo0, hi0); upk2(acc1, lo1, hi1);
    upk2(acc2, lo2, hi2); upk2(acc3, lo3, hi3);
    float* outc = g_part + (size_t)c * BN;
    *reinterpret_cast<float4*>(outc + (size_t)(2 * p) * N + a0) =
        make_float4(lo0, lo1, lo2, lo3);
    *reinterpret_cast<float4*>(outc + (size_t)(2 * p + 1) * N + a0) =
        make_float4(hi0, hi1, hi2, hi3);
}

// Kernel C: sum the 32 planes, v = 1 - exp(-S), seed clamp, write pred (+ out).
// 2 threads per output scalar (even lane: chunks 0..15, odd: 16..31), each with
// 8 independent accumulator chains; partner combine via shfl.xor(1).
// 65536 threads = 256 blocks x 256 -> 2x the outstanding loads of R5's version.
__global__ void __launch_bounds__(256) propC(const int2* __restrict__ seed, int nseeds,
                                             float* __restrict__ final_out) {
    __shared__ int s_flat[128];
    const int tid = threadIdx.x;
    if (tid < nseeds) {
        int2 s = seed[tid];
        s_flat[tid] = s.x * N + s.y;
    }
    __syncthreads();

    const int g2 = blockIdx.x * 256 + tid;
    const int o = g2 >> 1;             // output index
    const int half = g2 & 1;           // chunk half
    const int cbase = half * 16;

    float a0 = 0.f, a1 = 0.f, a2 = 0.f, a3 = 0.f;
    float a4 = 0.f, a5 = 0.f, a6 = 0.f, a7 = 0.f;
#pragma unroll
    for (int c = 0; c < 16; c += 8) {
        a0 += __ldg(&g_part[(size_t)(cbase + c + 0) * BN + o]);
        a1 += __ldg(&g_part[(size_t)(cbase + c + 1) * BN + o]);
        a2 += __ldg(&g_part[(size_t)(cbase + c + 2) * BN + o]);
        a3 += __ldg(&g_part[(size_t)(cbase + c + 3) * BN + o]);
        a4 += __ldg(&g_part[(size_t)(cbase + c + 4) * BN + o]);
        a5 += __ldg(&g_part[(size_t)(cbase + c + 5) * BN + o]);
        a6 += __ldg(&g_part[(size_t)(cbase + c + 6) * BN + o]);
        a7 += __ldg(&g_part[(size_t)(cbase + c + 7) * BN + o]);
    }
    float s = ((a0 + a1) + (a2 + a3)) + ((a4 + a5) + (a6 + a7));
    s += __shfl_xor_sync(0xffffffffu, s, 1);   // combine the two halves

    if (half == 0) {
        float v = 1.0f - __expf(-s);
        for (int k = 0; k < nseeds; k++)
            if (s_flat[k] == o) v = 1.0f;
        g_pred[o] = v;
        if (final_out) final_out[o] = v;
    }
}

extern "C" void kernel_launch(void* const* d_in, const int* in_sizes, int n_in,
                              void* d_out, int out_size) {
    const float* preds = (const float*)d_in[0];      // [B, N] fp32
    const float* P = (const float*)d_in[1];          // [N, N] fp32, P[b*N + a]
    const int2* seed = (const int2*)d_in[2];         // [NSEEDS, 2] int32 (b, n)
    int nseeds = in_sizes[2] / 2;
    if (nseeds > 128) nseeds = 128;
    float* out = (float*)d_out;

    dim3 gridA(NTILE, NCHUNK);      // (32, 32) = 1024 blocks
    dim3 gridC(2 * BN / 256);       // 256 blocks

    for (int t = 0; t < NITER; t++) {
        propA<<<gridA, BLOCK_A>>>(P, preds, t == 0 ? 1 : 0);
        propC<<<gridC, 256>>>(seed, nseeds, (t == NITER - 1) ? out : nullptr);
    }
}